// round 16
// baseline (speedup 1.0000x reference)
#include <cuda_runtime.h>
#include <cuda_bf16.h>
#include <cstdint>

#define M_PTS   200000
#define N_CAM   6
#define C_IMG   96
#define H_FEAT  32
#define W_FEAT  88
#define PTS_DIM 128
#define KIN     224           // 128 + 96
#define GZ      32
#define GY      512
#define GX      448
#define GRID_N  (GZ*GY*GX)

#define NTAP_O   26
#define PAIR_CAP 200000

// merged-kernel block dispatch
#define TRANS_TOT  (N_CAM*H_FEAT*W_FEAT*C_IMG)
#define NB_TRANS   ((TRANS_TOT + 255)/256)
#define NB_GRID    (GRID_N/4/256)
#define WT_TOT     (27*KIN*PTS_DIM)
#define NB_WT      ((WT_TOT + 255)/256)
#define NB_SETUP   1
#define NB_MEGA1   (NB_TRANS + NB_GRID + NB_WT + NB_SETUP)

#define NB_SAMPLE  (M_PTS/8)
#define NB_BPAIR   ((M_PTS + 255)/256)
#define NB_ZACC    ((M_PTS*PTS_DIM/4 + 255)/256)
#define NB_MEGA2   (NB_SAMPLE + NB_BPAIR + NB_ZACC)

typedef unsigned u32;

// ---- conv smem (u32 units), per-block N-half design ----
// B: 64 n-rows, stride 120 (proven conflict-free)
// A: full 128 rows, 7 pieces of 2 chunks, double-buffered, stride 24
#define B_S 120
#define A2_S 24
#define SM_BHI  0
#define SM_BLO  (64*B_S*4)                // 30720
#define SM_A    (2*64*B_S*4)              // 61440
#define A_BUF_U32 (128*A2_S)              // 3072 u32 = 12288 B per (buf,hi/lo)
#define SMEM_CONV (SM_A + 4*A_BUF_U32*4)  // 110592 (108 KB) -> 2 blocks/SM

// mma.sync m16n8k16 row.col f32.bf16.bf16.f32
#define MMA_BF16(d, a, b0v, b1v) \
    asm volatile("mma.sync.aligned.m16n8k16.row.col.f32.bf16.bf16.f32 " \
        "{%0,%1,%2,%3}, {%4,%5,%6,%7}, {%8,%9}, {%0,%1,%2,%3};" \
        : "+f"((d)[0]), "+f"((d)[1]), "+f"((d)[2]), "+f"((d)[3]) \
        : "r"((a)[0]), "r"((a)[1]), "r"((a)[2]), "r"((a)[3]), "r"(b0v), "r"(b1v))

#define PACK_BF162(r, f0, f1) \
    asm("cvt.rn.bf16x2.f32 %0, %1, %2;" : "=r"(r) : "f"(f1), "f"(f0))   // lo half = f0

// truncation split of a float pair into hi bf16x2 (exact prefix) + lo bf16x2 (rn residual)
__device__ __forceinline__ void split2(float x, float y, u32& hi, u32& lo) {
    u32 b0 = __float_as_uint(x), b1 = __float_as_uint(y);
    hi = (b1 & 0xFFFF0000u) | (b0 >> 16);
    float l0 = x - __uint_as_float(b0 & 0xFFFF0000u);
    float l1 = y - __uint_as_float(b1 & 0xFFFF0000u);
    PACK_BF162(lo, l0, l1);
}

// k-pair interleave: orig u32 col c -> position so cols (t, t+4) are adjacent
__device__ __forceinline__ int icol(int c) {
    int w = c & 7;
    return (c & ~7) + ((w < 4) ? (w << 1) : (((w - 4) << 1) | 1));
}

// ---------------- device globals ----------------
__device__ float g_imgT[N_CAM*H_FEAT*W_FEAT*C_IMG];
__device__ int   g_grid[GRID_N];
__device__ float g_sampled[(size_t)M_PTS*C_IMG];
__device__ float g_acc[(size_t)M_PTS*PTS_DIM];
__device__ int2  g_pairs[(size_t)NTAP_O*PAIR_CAP];
__device__ int   g_np[NTAP_O];
__device__ float g_cam[N_CAM*24];
__device__ float g_bnscale[PTS_DIM];
__device__ float g_bnbias[PTS_DIM];
__device__ __nv_bfloat16 g_wt_hi[27*PTS_DIM*KIN];   // [k][n][kin]
__device__ __nv_bfloat16 g_wt_lo[27*PTS_DIM*KIN];

// ================= mega kernel 1: transpose + grid init + weight split + setup ============
__global__ void mega_setup_kernel(const float* __restrict__ img,
                                  const float* __restrict__ convw,
                                  const float* __restrict__ l2i,
                                  const float* __restrict__ iaug,
                                  const float* __restrict__ laug,
                                  const float* __restrict__ gamma,
                                  const float* __restrict__ beta,
                                  const float* __restrict__ mean,
                                  const float* __restrict__ var) {
    int b = blockIdx.x;
    if (b < NB_TRANS) {
        int o = b * 256 + threadIdx.x;
        if (o < TRANS_TOT) {
            int c = o % C_IMG; int rest = o / C_IMG;
            int x = rest % W_FEAT; rest /= W_FEAT;
            int y = rest % H_FEAT; int n = rest / H_FEAT;
            g_imgT[o] = img[(((size_t)n*C_IMG + c)*H_FEAT + y)*W_FEAT + x];
        }
        return;
    }
    b -= NB_TRANS;
    if (b < NB_GRID) {
        int idx = b * 256 + threadIdx.x;
        ((int4*)g_grid)[idx] = make_int4(-1,-1,-1,-1);
        return;
    }
    b -= NB_GRID;
    if (b < NB_WT) {
        int o = b * 256 + threadIdx.x;   // o indexes [k][n][kin]
        if (o < WT_TOT) {
            int kin = o % KIN; int rest = o / KIN;
            int n = rest % PTS_DIM; int k = rest / PTS_DIM;
            float w = convw[((size_t)k*KIN + kin)*PTS_DIM + n];
            u32 wb = __float_as_uint(w);
            float hi = __uint_as_float(wb & 0xFFFF0000u);
            float r = w - hi;
            g_wt_hi[o] = __float2bfloat16(hi);
            g_wt_lo[o] = __float2bfloat16(r);
        }
        return;
    }
    // setup block
    int t = threadIdx.x;
    if (t < PTS_DIM) {
        float s = rsqrtf(var[t] + 1e-5f) * gamma[t];
        g_bnscale[t] = s;
        g_bnbias[t]  = beta[t] - mean[t] * s;
    }
    if (t >= 128 && t < 128 + NTAP_O) g_np[t-128] = 0;
    if (t == 0) {
        float a0=laug[0],a1=laug[1],a2=laug[2];
        float a3=laug[4],a4=laug[5],a5=laug[6];
        float a6=laug[8],a7=laug[9],a8=laug[10];
        float tx=laug[3], ty=laug[7], tz=laug[11];
        float det = a0*(a4*a8-a5*a7) - a1*(a3*a8-a5*a6) + a2*(a3*a7-a4*a6);
        float id = 1.0f/det;
        float inv[9] = {
            (a4*a8-a5*a7)*id, (a2*a7-a1*a8)*id, (a1*a5-a2*a4)*id,
            (a5*a6-a3*a8)*id, (a0*a8-a2*a6)*id, (a2*a3-a0*a5)*id,
            (a3*a7-a4*a6)*id, (a1*a6-a0*a7)*id, (a0*a4-a1*a3)*id };
        for (int n = 0; n < N_CAM; n++) {
            const float* L = l2i + n*16;
            float P[9], q[3];
            for (int r = 0; r < 3; r++) {
                for (int c = 0; c < 3; c++)
                    P[r*3+c] = L[r*4+0]*inv[0*3+c] + L[r*4+1]*inv[1*3+c] + L[r*4+2]*inv[2*3+c];
                q[r] = L[r*4+3] - (P[r*3+0]*tx + P[r*3+1]*ty + P[r*3+2]*tz);
            }
            float* gc = g_cam + n*24;
            for (int r = 0; r < 3; r++) {
                gc[r*4+0]=P[r*3+0]; gc[r*4+1]=P[r*3+1]; gc[r*4+2]=P[r*3+2]; gc[r*4+3]=q[r];
            }
            const float* A = iaug + n*16;
            for (int r = 0; r < 2; r++) {
                gc[12+r*4+0]=A[r*4+0]; gc[12+r*4+1]=A[r*4+1]; gc[12+r*4+2]=A[r*4+2]; gc[12+r*4+3]=A[r*4+3];
            }
        }
    }
}

// ================= scatter =================
__global__ void scatter_kernel(const int* __restrict__ vc) {
    int i = blockIdx.x * 256 + threadIdx.x;
    if (i >= M_PTS) return;
    int4 c4 = ((const int4*)vc)[i];
    atomicMax(&g_grid[(c4.y*GY + c4.z)*GX + c4.w], i);
}

// ================= mega kernel 2: sample + build_pairs + zero_acc =================
__device__ __forceinline__ void sample_body(const int* __restrict__ vc, int blk) {
    int warp = blk * 8 + (threadIdx.x >> 5);
    int lane = threadIdx.x & 31;
    if (warp >= M_PTS) return;
    int4 c4 = ((const int4*)vc)[warp];
    float px = (float)c4.w, py = (float)c4.z, pz = (float)c4.y;

    float x0f = 0.f, y0f = 0.f, wx1v = 0.f, wy1v = 0.f;
    int vmask = 0;
    if (lane < N_CAM) {
        const float* cam = g_cam + lane*24;
        float X = cam[0]*px + cam[1]*py + cam[2]*pz  + cam[3];
        float Y = cam[4]*px + cam[5]*py + cam[6]*pz  + cam[7];
        float Z = cam[8]*px + cam[9]*py + cam[10]*pz + cam[11];
        float z = fminf(fmaxf(Z, 1e-5f), 100000.0f);
        float rz = 1.0f / z;
        float vx = X*rz, vy = Y*rz;
        float u = cam[12]*vx + cam[13]*vy + cam[14]*z + cam[15];
        float v = cam[16]*vx + cam[17]*vy + cam[18]*z + cam[19];
        float xf = u * (87.0f/704.0f);
        float yf = v * (31.0f/256.0f);
        x0f = floorf(xf); y0f = floorf(yf);
        wx1v = xf - x0f;  wy1v = yf - y0f;
        bool xi0 = (x0f >= 0.0f) && (x0f <= 87.0f);
        bool xi1 = (x0f + 1.0f >= 0.0f) && (x0f + 1.0f <= 87.0f);
        bool yi0 = (y0f >= 0.0f) && (y0f <= 31.0f);
        bool yi1 = (y0f + 1.0f >= 0.0f) && (y0f + 1.0f <= 31.0f);
        vmask = (xi0 && yi0) | ((xi1 && yi0) << 1) | ((xi0 && yi1) << 2) | ((xi1 && yi1) << 3);
    }

    float4 acc = make_float4(0.f,0.f,0.f,0.f);
    bool ld = lane < 24;
    #pragma unroll
    for (int n = 0; n < N_CAM; n++) {
        float bx0 = __shfl_sync(0xffffffffu, x0f,  n);
        float by0 = __shfl_sync(0xffffffffu, y0f,  n);
        float wx1 = __shfl_sync(0xffffffffu, wx1v, n);
        float wy1 = __shfl_sync(0xffffffffu, wy1v, n);
        int   vm  = __shfl_sync(0xffffffffu, vmask, n);
        float wx0 = 1.0f - wx1, wy0 = 1.0f - wy1;
        int ix = (int)bx0, iy = (int)by0;
        const float* base00 = g_imgT + (((size_t)n*H_FEAT + iy)*W_FEAT + ix) * C_IMG;
        float cw[4] = {wx0*wy0, wx1*wy0, wx0*wy1, wx1*wy1};
        const int doff[4] = {0, C_IMG, W_FEAT*C_IMG, W_FEAT*C_IMG + C_IMG};
        #pragma unroll
        for (int q = 0; q < 4; q++) {
            if (((vm >> q) & 1) && ld) {
                float4 f = __ldg((const float4*)(base00 + doff[q]) + lane);
                float w = cw[q];
                acc.x += w*f.x; acc.y += w*f.y; acc.z += w*f.z; acc.w += w*f.w;
            }
        }
    }
    if (ld)
        ((float4*)(g_sampled + (size_t)warp*C_IMG))[lane] = acc;
}

__device__ __forceinline__ void build_pairs_body(const int* __restrict__ vc, int blk) {
    int tid = threadIdx.x;
    int i = blk * 256 + tid;
    int lane = tid & 31;
    bool live = i < M_PTS;
    int4 c4 = live ? ((const int4*)vc)[i] : make_int4(0,0,0,0);

    #pragma unroll 1
    for (int t = 0; t < NTAP_O; t++) {
        int k = (t < 13) ? t : t + 1;
        int dz = k/9 - 1, dy = (k/3)%3 - 1, dx = k%3 - 1;
        int nz = c4.y + dz, ny = c4.z + dy, nx = c4.w + dx;
        bool valid = live && nz >= 0 && nz < GZ && ny >= 0 && ny < GY && nx >= 0 && nx < GX;
        int nid = -1;
        if (valid) nid = __ldg(&g_grid[(nz*GY + ny)*GX + nx]);
        valid = valid && (nid >= 0);
        unsigned m = __ballot_sync(0xffffffffu, valid);
        if (m != 0) {
            int ldr = __ffs(m) - 1;
            int base = 0;
            if (lane == ldr) base = atomicAdd(&g_np[t], __popc(m));
            base = __shfl_sync(0xffffffffu, base, ldr);
            if (valid) {
                int rank = __popc(m & ((1u << lane) - 1u));
                g_pairs[(size_t)t*PAIR_CAP + base + rank] = make_int2(i, nid);
            }
        }
    }
}

__global__ void __launch_bounds__(256, 4)
mega_mid_kernel(const int* __restrict__ vc) {
    int b = blockIdx.x;
    if (b < NB_SAMPLE) { sample_body(vc, b); return; }
    b -= NB_SAMPLE;
    if (b < NB_BPAIR)  { build_pairs_body(vc, b); return; }
    b -= NB_BPAIR;
    {
        int idx = b * 256 + threadIdx.x;
        if (idx < (M_PTS*PTS_DIM)/4) ((float4*)g_acc)[idx] = make_float4(0.f,0.f,0.f,0.f);
    }
}

// ====== sparse conv: mma.sync bf16-split, N-halved blocks (256 thr, 2 blocks/SM) ======
template<bool SELF>
__global__ void __launch_bounds__(256, 2)
conv_mma_kernel(const float* __restrict__ pts,
                const int*   __restrict__ vc,
                float*       __restrict__ out) {
    extern __shared__ char smem[];
    u32* s_bhi = (u32*)(smem + SM_BHI);
    u32* s_blo = (u32*)(smem + SM_BLO);
    u32* a_base = (u32*)(smem + SM_A);   // [buf0_hi][buf0_lo][buf1_hi][buf1_lo]
    __shared__ int s_out[128];
    __shared__ int s_nid[128];
    __shared__ float s_sc[64], s_bi[64];

    int tid = threadIdx.x;
    int wid = tid >> 5;                  // 0..7
    int lane = tid & 31;
    int g = lane >> 2, t = lane & 3;
    int warpRow = (wid >> 1) * 32;       // 4 M-groups
    int warpCol = (wid & 1) * 32;        // 2 N-groups (within 64-col half)
    int nh = blockIdx.z;                 // N-half: cols [nh*64, nh*64+64)

    // staging role: each thread loads 4 rows' float4 within a 32-float piece
    int rw = lane >> 3;                  // 0..3
    int cq = lane & 7;                   // float4 index within piece
    int arow = wid*4 + rw;               // 0..31; +32*i covers 128 rows
    int pos0 = icol(cq*2), pos1 = icol(cq*2 + 1);

    int k, np, tile0, tstep, tpair;
    if (SELF) { k = 13; np = M_PTS; tile0 = blockIdx.x; tstep = gridDim.x; tpair = 0; }
    else {
        int tt = blockIdx.y;
        k = (tt < 13) ? tt : tt + 1;
        np = g_np[tt];
        tile0 = blockIdx.x; tstep = gridDim.x; tpair = tt;
    }

    // load B hi/lo (our 64-row half) into smem with k-pair interleave
    {
        const u32* src_h = (const u32*)(g_wt_hi + (size_t)k*PTS_DIM*KIN) + nh*64*112;
        const u32* src_l = (const u32*)(g_wt_lo + (size_t)k*PTS_DIM*KIN) + nh*64*112;
        for (int i = tid; i < 64*112; i += 256) {
            int n = i / 112, kp = i % 112;
            int dst = n*B_S + icol(kp);
            s_bhi[dst] = __ldg(src_h + i);
            s_blo[dst] = __ldg(src_l + i);
        }
        if (SELF && tid < 64) {
            s_sc[tid] = g_bnscale[nh*64 + tid];
            s_bi[tid] = g_bnbias[nh*64 + tid];
        }
    }
    __syncthreads();

    for (int tile = tile0; tile*128 < np; tile += tstep) {
        __syncthreads();
        // tile metadata
        if (tid < 128) {
            int r = tile*128 + tid;
            int o = -1, nid = 0;
            if (r < np) {
                if (SELF) {
                    int4 c4 = ((const int4*)vc)[r];
                    o = r;
                    nid = __ldg(&g_grid[(c4.y*GY + c4.z)*GX + c4.w]);
                } else {
                    int2 pr = g_pairs[(size_t)tpair*PAIR_CAP + r];
                    o = pr.x; nid = pr.y;
                }
            }
            s_out[tid] = o;
            s_nid[tid] = nid;
        }
        __syncthreads();

        float acc[2][4][4];
        #pragma unroll
        for (int mi = 0; mi < 2; mi++)
            #pragma unroll
            for (int ni = 0; ni < 4; ni++)
                #pragma unroll
                for (int j = 0; j < 4; j++) acc[mi][ni][j] = 0.0f;

        const float* rp[4]; const float* rs[4];
        #pragma unroll
        for (int i = 0; i < 4; i++) {
            int nid = s_nid[arow + 32*i];
            rp[i] = pts + (size_t)nid*PTS_DIM;
            rs[i] = g_sampled + (size_t)nid*C_IMG - PTS_DIM;   // indexed by fcol
        }

        // prologue: LDG + STS piece 0 into buf 0
        float4 v[4];
        {
            int fcol = cq*4;
            #pragma unroll
            for (int i = 0; i < 4; i++) v[i] = __ldg((const float4*)(rp[i] + fcol));
            u32* ah = a_base;
            u32* al = a_base + A_BUF_U32;
            #pragma unroll
            for (int i = 0; i < 4; i++) {
                int rbase = (arow + 32*i)*A2_S;
                u32 h0,l0,h1,l1;
                split2(v[i].x, v[i].y, h0, l0); split2(v[i].z, v[i].w, h1, l1);
                ah[rbase + pos0] = h0; ah[rbase + pos1] = h1;
                al[rbase + pos0] = l0; al[rbase + pos1] = l1;
            }
        }
        __syncthreads();

        #pragma unroll 1
        for (int p = 0; p < 7; p++) {
            // issue LDGs for piece p+1
            if (p < 6) {
                int fcol = (p+1)*32 + cq*4;
                #pragma unroll
                for (int i = 0; i < 4; i++) {
                    const float* s = (fcol < PTS_DIM) ? (rp[i] + fcol) : (rs[i] + fcol);
                    v[i] = __ldg((const float4*)s);
                }
            }

            // MMA on buffer p&1 (2 chunks)
            {
                const u32* ah = a_base + (p & 1)*2*A_BUF_U32;
                const u32* al = ah + A_BUF_U32;
                #pragma unroll
                for (int cl = 0; cl < 2; cl++) {
                    int cg = p*2 + cl;
                    u32 fa_h[2][4], fa_l[2][4];
                    #pragma unroll
                    for (int mi = 0; mi < 2; mi++) {
                        int r0 = warpRow + mi*16 + g;
                        int off0 = r0*A2_S + cl*8 + 2*t;
                        int off1 = off0 + 8*A2_S;
                        uint2 ph0 = *(const uint2*)&ah[off0];
                        uint2 ph1 = *(const uint2*)&ah[off1];
                        uint2 pl0 = *(const uint2*)&al[off0];
                        uint2 pl1 = *(const uint2*)&al[off1];
                        fa_h[mi][0] = ph0.x; fa_h[mi][2] = ph0.y;
                        fa_h[mi][1] = ph1.x; fa_h[mi][3] = ph1.y;
                        fa_l[mi][0] = pl0.x; fa_l[mi][2] = pl0.y;
                        fa_l[mi][1] = pl1.x; fa_l[mi][3] = pl1.y;
                    }
                    #pragma unroll
                    for (int ni = 0; ni < 4; ni++) {
                        int n = warpCol + ni*8 + g;     // local n within half
                        int off = n*B_S + cg*8 + 2*t;
                        uint2 bh = *(const uint2*)&s_bhi[off];
                        uint2 bl = *(const uint2*)&s_blo[off];
                        #pragma unroll
                        for (int mi = 0; mi < 2; mi++) {
                            MMA_BF16(acc[mi][ni], fa_h[mi], bh.x, bh.y);
                            MMA_BF16(acc[mi][ni], fa_h[mi], bl.x, bl.y);
                            MMA_BF16(acc[mi][ni], fa_l[mi], bh.x, bh.y);
                        }
                    }
                }
            }

            // convert + STS piece p+1 into buffer (p+1)&1
            if (p < 6) {
                u32* ah = a_base + ((p+1) & 1)*2*A_BUF_U32;
                u32* al = ah + A_BUF_U32;
                #pragma unroll
                for (int i = 0; i < 4; i++) {
                    int rbase = (arow + 32*i)*A2_S;
                    u32 h0,l0,h1,l1;
                    split2(v[i].x, v[i].y, h0, l0); split2(v[i].z, v[i].w, h1, l1);
                    ah[rbase + pos0] = h0; ah[rbase + pos1] = h1;
                    al[rbase + pos0] = l0; al[rbase + pos1] = l1;
                }
                __syncthreads();
            }
        }

        // epilogue from registers (global cols = nh*64 + local)
        #pragma unroll
        for (int mi = 0; mi < 2; mi++) {
            int r0 = warpRow + mi*16 + g;
            int o0 = s_out[r0], o1 = s_out[r0 + 8];
            #pragma unroll
            for (int ni = 0; ni < 4; ni++) {
                int nl = warpCol + ni*8 + t*2;
                int gn = nh*64 + nl;
                if (SELF) {
                    float sc0 = s_sc[nl], sc1 = s_sc[nl+1];
                    float bi0 = s_bi[nl], bi1 = s_bi[nl+1];
                    if (o0 >= 0) {
                        float a0 = g_acc[(size_t)o0*PTS_DIM + gn];
                        float a1 = g_acc[(size_t)o0*PTS_DIM + gn + 1];
                        out[(size_t)o0*PTS_DIM + gn]     = fmaxf((acc[mi][ni][0]+a0)*sc0+bi0, 0.f);
                        out[(size_t)o0*PTS_DIM + gn + 1] = fmaxf((acc[mi][ni][1]+a1)*sc1+bi1, 0.f);
                    }
                    if (o1 >= 0) {
                        float a2 = g_acc[(size_t)o1*PTS_DIM + gn];
                        float a3 = g_acc[(size_t)o1*PTS_DIM + gn + 1];
                        out[(size_t)o1*PTS_DIM + gn]     = fmaxf((acc[mi][ni][2]+a2)*sc0+bi0, 0.f);
                        out[(size_t)o1*PTS_DIM + gn + 1] = fmaxf((acc[mi][ni][3]+a3)*sc1+bi1, 0.f);
                    }
                } else {
                    if (o0 >= 0) {
                        atomicAdd(&g_acc[(size_t)o0*PTS_DIM + gn],     acc[mi][ni][0]);
                        atomicAdd(&g_acc[(size_t)o0*PTS_DIM + gn + 1], acc[mi][ni][1]);
                    }
                    if (o1 >= 0) {
                        atomicAdd(&g_acc[(size_t)o1*PTS_DIM + gn],     acc[mi][ni][2]);
                        atomicAdd(&g_acc[(size_t)o1*PTS_DIM + gn + 1], acc[mi][ni][3]);
                    }
                }
            }
        }
    }
}

// ---------------- launch ----------------
extern "C" void kernel_launch(void* const* d_in, const int* in_sizes, int n_in,
                              void* d_out, int out_size) {
    const float* pts   = (const float*)d_in[0];
    const int*   vc    = (const int*)  d_in[1];
    const float* img   = (const float*)d_in[2];
    const float* l2i   = (const float*)d_in[3];
    const float* iaug  = (const float*)d_in[4];
    const float* laug  = (const float*)d_in[5];
    const float* convw = (const float*)d_in[6];
    const float* gamma = (const float*)d_in[7];
    const float* beta  = (const float*)d_in[8];
    const float* mean  = (const float*)d_in[9];
    const float* var   = (const float*)d_in[10];
    float* out = (float*)d_out;

    cudaFuncSetAttribute(conv_mma_kernel<false>, cudaFuncAttributeMaxDynamicSharedMemorySize, SMEM_CONV);
    cudaFuncSetAttribute(conv_mma_kernel<true>,  cudaFuncAttributeMaxDynamicSharedMemorySize, SMEM_CONV);

    mega_setup_kernel<<<NB_MEGA1, 256>>>(img, convw, l2i, iaug, laug, gamma, beta, mean, var);
    scatter_kernel<<<(M_PTS + 255)/256, 256>>>(vc);
    mega_mid_kernel<<<NB_MEGA2, 256>>>(vc);
    conv_mma_kernel<false><<<dim3(16, NTAP_O, 2), 256, SMEM_CONV>>>(pts, vc, out);   // <-- ncu slot
    conv_mma_kernel<true ><<<dim3(296, 1, 2),     256, SMEM_CONV>>>(pts, vc, out);
}

// round 17
// speedup vs baseline: 1.0372x; 1.0372x over previous
#include <cuda_runtime.h>
#include <cuda_bf16.h>
#include <cstdint>

#define M_PTS   200000
#define N_CAM   6
#define C_IMG   96
#define H_FEAT  32
#define W_FEAT  88
#define PTS_DIM 128
#define KIN     224           // 128 + 96
#define GZ      32
#define GY      512
#define GX      448
#define GRID_N  (GZ*GY*GX)

#define NTAP_O   26
#define PAIR_CAP 200000

// merged-kernel block dispatch
#define TRANS_TOT  (N_CAM*H_FEAT*W_FEAT*C_IMG)
#define NB_TRANS   ((TRANS_TOT + 255)/256)
#define NB_GRID    (GRID_N/4/256)
#define WT_TOT     (27*KIN*PTS_DIM)
#define NB_WT      ((WT_TOT + 255)/256)
#define NB_SETUP   1
#define NB_MEGA1   (NB_TRANS + NB_GRID + NB_WT + NB_SETUP)

#define NB_SAMPLE  (M_PTS/8)
#define NB_BPAIR   ((M_PTS + 255)/256)
#define NB_ZACC    ((M_PTS*PTS_DIM/4 + 255)/256)
#define NB_MEGA2   (NB_SAMPLE + NB_BPAIR + NB_ZACC)

typedef unsigned u32;

// ---- shared constants ----
#define A2_S 24
#define A_BUF_U32 (128*A2_S)              // 3072 u32 = 12288 B per (buf,hi/lo)
#define B_S 120

// split (non-self) kernel smem: B 64 rows
#define SMS_BHI  0
#define SMS_BLO  (64*B_S*4)               // 30720
#define SMS_A    (2*64*B_S*4)             // 61440
#define SMEM_SPLIT (SMS_A + 4*A_BUF_U32*4)  // 110592 -> 2 blocks/SM

// full (self) kernel smem: B 128 rows
#define SMF_BHI  0
#define SMF_BLO  (128*B_S*4)              // 61440
#define SMF_A    (2*128*B_S*4)            // 122880
#define SMEM_FULL (SMF_A + 4*A_BUF_U32*4)   // 172032 -> 1 block/SM

// mma.sync m16n8k16 row.col f32.bf16.bf16.f32
#define MMA_BF16(d, a, b0v, b1v) \
    asm volatile("mma.sync.aligned.m16n8k16.row.col.f32.bf16.bf16.f32 " \
        "{%0,%1,%2,%3}, {%4,%5,%6,%7}, {%8,%9}, {%0,%1,%2,%3};" \
        : "+f"((d)[0]), "+f"((d)[1]), "+f"((d)[2]), "+f"((d)[3]) \
        : "r"((a)[0]), "r"((a)[1]), "r"((a)[2]), "r"((a)[3]), "r"(b0v), "r"(b1v))

#define PACK_BF162(r, f0, f1) \
    asm("cvt.rn.bf16x2.f32 %0, %1, %2;" : "=r"(r) : "f"(f1), "f"(f0))   // lo half = f0

__device__ __forceinline__ void split2(float x, float y, u32& hi, u32& lo) {
    u32 b0 = __float_as_uint(x), b1 = __float_as_uint(y);
    hi = (b1 & 0xFFFF0000u) | (b0 >> 16);
    float l0 = x - __uint_as_float(b0 & 0xFFFF0000u);
    float l1 = y - __uint_as_float(b1 & 0xFFFF0000u);
    PACK_BF162(lo, l0, l1);
}

__device__ __forceinline__ int icol(int c) {
    int w = c & 7;
    return (c & ~7) + ((w < 4) ? (w << 1) : (((w - 4) << 1) | 1));
}

// ---------------- device globals ----------------
__device__ float g_imgT[N_CAM*H_FEAT*W_FEAT*C_IMG];
__device__ int   g_grid[GRID_N];
__device__ float g_sampled[(size_t)M_PTS*C_IMG];
__device__ float g_acc[(size_t)M_PTS*PTS_DIM];
__device__ int2  g_pairs[(size_t)NTAP_O*PAIR_CAP];
__device__ int   g_np[NTAP_O];
__device__ float g_cam[N_CAM*24];
__device__ float g_bnscale[PTS_DIM];
__device__ float g_bnbias[PTS_DIM];
__device__ __nv_bfloat16 g_wt_hi[27*PTS_DIM*KIN];   // [k][n][kin]
__device__ __nv_bfloat16 g_wt_lo[27*PTS_DIM*KIN];

// ================= mega kernel 1 =================
__global__ void mega_setup_kernel(const float* __restrict__ img,
                                  const float* __restrict__ convw,
                                  const float* __restrict__ l2i,
                                  const float* __restrict__ iaug,
                                  const float* __restrict__ laug,
                                  const float* __restrict__ gamma,
                                  const float* __restrict__ beta,
                                  const float* __restrict__ mean,
                                  const float* __restrict__ var) {
    int b = blockIdx.x;
    if (b < NB_TRANS) {
        int o = b * 256 + threadIdx.x;
        if (o < TRANS_TOT) {
            int c = o % C_IMG; int rest = o / C_IMG;
            int x = rest % W_FEAT; rest /= W_FEAT;
            int y = rest % H_FEAT; int n = rest / H_FEAT;
            g_imgT[o] = img[(((size_t)n*C_IMG + c)*H_FEAT + y)*W_FEAT + x];
        }
        return;
    }
    b -= NB_TRANS;
    if (b < NB_GRID) {
        int idx = b * 256 + threadIdx.x;
        ((int4*)g_grid)[idx] = make_int4(-1,-1,-1,-1);
        return;
    }
    b -= NB_GRID;
    if (b < NB_WT) {
        int o = b * 256 + threadIdx.x;
        if (o < WT_TOT) {
            int kin = o % KIN; int rest = o / KIN;
            int n = rest % PTS_DIM; int k = rest / PTS_DIM;
            float w = convw[((size_t)k*KIN + kin)*PTS_DIM + n];
            u32 wb = __float_as_uint(w);
            float hi = __uint_as_float(wb & 0xFFFF0000u);
            float r = w - hi;
            g_wt_hi[o] = __float2bfloat16(hi);
            g_wt_lo[o] = __float2bfloat16(r);
        }
        return;
    }
    int t = threadIdx.x;
    if (t < PTS_DIM) {
        float s = rsqrtf(var[t] + 1e-5f) * gamma[t];
        g_bnscale[t] = s;
        g_bnbias[t]  = beta[t] - mean[t] * s;
    }
    if (t >= 128 && t < 128 + NTAP_O) g_np[t-128] = 0;
    if (t == 0) {
        float a0=laug[0],a1=laug[1],a2=laug[2];
        float a3=laug[4],a4=laug[5],a5=laug[6];
        float a6=laug[8],a7=laug[9],a8=laug[10];
        float tx=laug[3], ty=laug[7], tz=laug[11];
        float det = a0*(a4*a8-a5*a7) - a1*(a3*a8-a5*a6) + a2*(a3*a7-a4*a6);
        float id = 1.0f/det;
        float inv[9] = {
            (a4*a8-a5*a7)*id, (a2*a7-a1*a8)*id, (a1*a5-a2*a4)*id,
            (a5*a6-a3*a8)*id, (a0*a8-a2*a6)*id, (a2*a3-a0*a5)*id,
            (a3*a7-a4*a6)*id, (a1*a6-a0*a7)*id, (a0*a4-a1*a3)*id };
        for (int n = 0; n < N_CAM; n++) {
            const float* L = l2i + n*16;
            float P[9], q[3];
            for (int r = 0; r < 3; r++) {
                for (int c = 0; c < 3; c++)
                    P[r*3+c] = L[r*4+0]*inv[0*3+c] + L[r*4+1]*inv[1*3+c] + L[r*4+2]*inv[2*3+c];
                q[r] = L[r*4+3] - (P[r*3+0]*tx + P[r*3+1]*ty + P[r*3+2]*tz);
            }
            float* gc = g_cam + n*24;
            for (int r = 0; r < 3; r++) {
                gc[r*4+0]=P[r*3+0]; gc[r*4+1]=P[r*3+1]; gc[r*4+2]=P[r*3+2]; gc[r*4+3]=q[r];
            }
            const float* A = iaug + n*16;
            for (int r = 0; r < 2; r++) {
                gc[12+r*4+0]=A[r*4+0]; gc[12+r*4+1]=A[r*4+1]; gc[12+r*4+2]=A[r*4+2]; gc[12+r*4+3]=A[r*4+3];
            }
        }
    }
}

// ================= scatter =================
__global__ void scatter_kernel(const int* __restrict__ vc) {
    int i = blockIdx.x * 256 + threadIdx.x;
    if (i >= M_PTS) return;
    int4 c4 = ((const int4*)vc)[i];
    atomicMax(&g_grid[(c4.y*GY + c4.z)*GX + c4.w], i);
}

// ================= mega kernel 2 =================
__device__ __forceinline__ void sample_body(const int* __restrict__ vc, int blk) {
    int warp = blk * 8 + (threadIdx.x >> 5);
    int lane = threadIdx.x & 31;
    if (warp >= M_PTS) return;
    int4 c4 = ((const int4*)vc)[warp];
    float px = (float)c4.w, py = (float)c4.z, pz = (float)c4.y;

    float x0f = 0.f, y0f = 0.f, wx1v = 0.f, wy1v = 0.f;
    int vmask = 0;
    if (lane < N_CAM) {
        const float* cam = g_cam + lane*24;
        float X = cam[0]*px + cam[1]*py + cam[2]*pz  + cam[3];
        float Y = cam[4]*px + cam[5]*py + cam[6]*pz  + cam[7];
        float Z = cam[8]*px + cam[9]*py + cam[10]*pz + cam[11];
        float z = fminf(fmaxf(Z, 1e-5f), 100000.0f);
        float rz = 1.0f / z;
        float vx = X*rz, vy = Y*rz;
        float u = cam[12]*vx + cam[13]*vy + cam[14]*z + cam[15];
        float v = cam[16]*vx + cam[17]*vy + cam[18]*z + cam[19];
        float xf = u * (87.0f/704.0f);
        float yf = v * (31.0f/256.0f);
        x0f = floorf(xf); y0f = floorf(yf);
        wx1v = xf - x0f;  wy1v = yf - y0f;
        bool xi0 = (x0f >= 0.0f) && (x0f <= 87.0f);
        bool xi1 = (x0f + 1.0f >= 0.0f) && (x0f + 1.0f <= 87.0f);
        bool yi0 = (y0f >= 0.0f) && (y0f <= 31.0f);
        bool yi1 = (y0f + 1.0f >= 0.0f) && (y0f + 1.0f <= 31.0f);
        vmask = (xi0 && yi0) | ((xi1 && yi0) << 1) | ((xi0 && yi1) << 2) | ((xi1 && yi1) << 3);
    }

    float4 acc = make_float4(0.f,0.f,0.f,0.f);
    bool ld = lane < 24;
    #pragma unroll
    for (int n = 0; n < N_CAM; n++) {
        float bx0 = __shfl_sync(0xffffffffu, x0f,  n);
        float by0 = __shfl_sync(0xffffffffu, y0f,  n);
        float wx1 = __shfl_sync(0xffffffffu, wx1v, n);
        float wy1 = __shfl_sync(0xffffffffu, wy1v, n);
        int   vm  = __shfl_sync(0xffffffffu, vmask, n);
        float wx0 = 1.0f - wx1, wy0 = 1.0f - wy1;
        int ix = (int)bx0, iy = (int)by0;
        const float* base00 = g_imgT + (((size_t)n*H_FEAT + iy)*W_FEAT + ix) * C_IMG;
        float cw[4] = {wx0*wy0, wx1*wy0, wx0*wy1, wx1*wy1};
        const int doff[4] = {0, C_IMG, W_FEAT*C_IMG, W_FEAT*C_IMG + C_IMG};
        #pragma unroll
        for (int q = 0; q < 4; q++) {
            if (((vm >> q) & 1) && ld) {
                float4 f = __ldg((const float4*)(base00 + doff[q]) + lane);
                float w = cw[q];
                acc.x += w*f.x; acc.y += w*f.y; acc.z += w*f.z; acc.w += w*f.w;
            }
        }
    }
    if (ld)
        ((float4*)(g_sampled + (size_t)warp*C_IMG))[lane] = acc;
}

__device__ __forceinline__ void build_pairs_body(const int* __restrict__ vc, int blk) {
    int tid = threadIdx.x;
    int i = blk * 256 + tid;
    int lane = tid & 31;
    bool live = i < M_PTS;
    int4 c4 = live ? ((const int4*)vc)[i] : make_int4(0,0,0,0);

    #pragma unroll 1
    for (int t = 0; t < NTAP_O; t++) {
        int k = (t < 13) ? t : t + 1;
        int dz = k/9 - 1, dy = (k/3)%3 - 1, dx = k%3 - 1;
        int nz = c4.y + dz, ny = c4.z + dy, nx = c4.w + dx;
        bool valid = live && nz >= 0 && nz < GZ && ny >= 0 && ny < GY && nx >= 0 && nx < GX;
        int nid = -1;
        if (valid) nid = __ldg(&g_grid[(nz*GY + ny)*GX + nx]);
        valid = valid && (nid >= 0);
        unsigned m = __ballot_sync(0xffffffffu, valid);
        if (m != 0) {
            int ldr = __ffs(m) - 1;
            int base = 0;
            if (lane == ldr) base = atomicAdd(&g_np[t], __popc(m));
            base = __shfl_sync(0xffffffffu, base, ldr);
            if (valid) {
                int rank = __popc(m & ((1u << lane) - 1u));
                g_pairs[(size_t)t*PAIR_CAP + base + rank] = make_int2(i, nid);
            }
        }
    }
}

__global__ void __launch_bounds__(256, 4)
mega_mid_kernel(const int* __restrict__ vc) {
    int b = blockIdx.x;
    if (b < NB_SAMPLE) { sample_body(vc, b); return; }
    b -= NB_SAMPLE;
    if (b < NB_BPAIR)  { build_pairs_body(vc, b); return; }
    b -= NB_BPAIR;
    {
        int idx = b * 256 + threadIdx.x;
        if (idx < (M_PTS*PTS_DIM)/4) ((float4*)g_acc)[idx] = make_float4(0.f,0.f,0.f,0.f);
    }
}

// ====== conv non-self: N-halved blocks (256 thr, 2 blocks/SM), atomic accumulate ======
__global__ void __launch_bounds__(256, 2)
conv_split_kernel(const float* __restrict__ pts,
                  const int*   __restrict__ vc,
                  float*       __restrict__ out) {
    extern __shared__ char smem[];
    u32* s_bhi = (u32*)(smem + SMS_BHI);
    u32* s_blo = (u32*)(smem + SMS_BLO);
    u32* a_base = (u32*)(smem + SMS_A);
    __shared__ int s_out[128];
    __shared__ int s_nid[128];

    int tid = threadIdx.x;
    int wid = tid >> 5;
    int lane = tid & 31;
    int g = lane >> 2, t = lane & 3;
    int warpRow = (wid >> 1) * 32;
    int warpCol = (wid & 1) * 32;
    int nh = blockIdx.z;

    int rw = lane >> 3;
    int cq = lane & 7;
    int arow = wid*4 + rw;
    int pos0 = icol(cq*2), pos1 = icol(cq*2 + 1);

    int tt = blockIdx.y;
    int k = (tt < 13) ? tt : tt + 1;
    int np = g_np[tt];
    int tile0 = blockIdx.x, tstep = gridDim.x, tpair = tt;

    {
        const u32* src_h = (const u32*)(g_wt_hi + (size_t)k*PTS_DIM*KIN) + nh*64*112;
        const u32* src_l = (const u32*)(g_wt_lo + (size_t)k*PTS_DIM*KIN) + nh*64*112;
        for (int i = tid; i < 64*112; i += 256) {
            int n = i / 112, kp = i % 112;
            int dst = n*B_S + icol(kp);
            s_bhi[dst] = __ldg(src_h + i);
            s_blo[dst] = __ldg(src_l + i);
        }
    }
    __syncthreads();

    for (int tile = tile0; tile*128 < np; tile += tstep) {
        __syncthreads();
        if (tid < 128) {
            int r = tile*128 + tid;
            int o = -1, nid = 0;
            if (r < np) {
                int2 pr = g_pairs[(size_t)tpair*PAIR_CAP + r];
                o = pr.x; nid = pr.y;
            }
            s_out[tid] = o;
            s_nid[tid] = nid;
        }
        __syncthreads();

        float acc[2][4][4];
        #pragma unroll
        for (int mi = 0; mi < 2; mi++)
            #pragma unroll
            for (int ni = 0; ni < 4; ni++)
                #pragma unroll
                for (int j = 0; j < 4; j++) acc[mi][ni][j] = 0.0f;

        const float* rp[4]; const float* rs[4];
        #pragma unroll
        for (int i = 0; i < 4; i++) {
            int nid = s_nid[arow + 32*i];
            rp[i] = pts + (size_t)nid*PTS_DIM;
            rs[i] = g_sampled + (size_t)nid*C_IMG - PTS_DIM;
        }

        float4 v[4];
        {
            int fcol = cq*4;
            #pragma unroll
            for (int i = 0; i < 4; i++) v[i] = __ldg((const float4*)(rp[i] + fcol));
            u32* ah = a_base;
            u32* al = a_base + A_BUF_U32;
            #pragma unroll
            for (int i = 0; i < 4; i++) {
                int rbase = (arow + 32*i)*A2_S;
                u32 h0,l0,h1,l1;
                split2(v[i].x, v[i].y, h0, l0); split2(v[i].z, v[i].w, h1, l1);
                ah[rbase + pos0] = h0; ah[rbase + pos1] = h1;
                al[rbase + pos0] = l0; al[rbase + pos1] = l1;
            }
        }
        __syncthreads();

        #pragma unroll 1
        for (int p = 0; p < 7; p++) {
            if (p < 6) {
                int fcol = (p+1)*32 + cq*4;
                #pragma unroll
                for (int i = 0; i < 4; i++) {
                    const float* s = (fcol < PTS_DIM) ? (rp[i] + fcol) : (rs[i] + fcol);
                    v[i] = __ldg((const float4*)s);
                }
            }
            {
                const u32* ah = a_base + (p & 1)*2*A_BUF_U32;
                const u32* al = ah + A_BUF_U32;
                #pragma unroll
                for (int cl = 0; cl < 2; cl++) {
                    int cg = p*2 + cl;
                    u32 fa_h[2][4], fa_l[2][4];
                    #pragma unroll
                    for (int mi = 0; mi < 2; mi++) {
                        int r0 = warpRow + mi*16 + g;
                        int off0 = r0*A2_S + cl*8 + 2*t;
                        int off1 = off0 + 8*A2_S;
                        uint2 ph0 = *(const uint2*)&ah[off0];
                        uint2 ph1 = *(const uint2*)&ah[off1];
                        uint2 pl0 = *(const uint2*)&al[off0];
                        uint2 pl1 = *(const uint2*)&al[off1];
                        fa_h[mi][0] = ph0.x; fa_h[mi][2] = ph0.y;
                        fa_h[mi][1] = ph1.x; fa_h[mi][3] = ph1.y;
                        fa_l[mi][0] = pl0.x; fa_l[mi][2] = pl0.y;
                        fa_l[mi][1] = pl1.x; fa_l[mi][3] = pl1.y;
                    }
                    #pragma unroll
                    for (int ni = 0; ni < 4; ni++) {
                        int n = warpCol + ni*8 + g;
                        int off = n*B_S + cg*8 + 2*t;
                        uint2 bh = *(const uint2*)&s_bhi[off];
                        uint2 bl = *(const uint2*)&s_blo[off];
                        #pragma unroll
                        for (int mi = 0; mi < 2; mi++) {
                            MMA_BF16(acc[mi][ni], fa_h[mi], bh.x, bh.y);
                            MMA_BF16(acc[mi][ni], fa_h[mi], bl.x, bl.y);
                            MMA_BF16(acc[mi][ni], fa_l[mi], bh.x, bh.y);
                        }
                    }
                }
            }
            if (p < 6) {
                u32* ah = a_base + ((p+1) & 1)*2*A_BUF_U32;
                u32* al = ah + A_BUF_U32;
                #pragma unroll
                for (int i = 0; i < 4; i++) {
                    int rbase = (arow + 32*i)*A2_S;
                    u32 h0,l0,h1,l1;
                    split2(v[i].x, v[i].y, h0, l0); split2(v[i].z, v[i].w, h1, l1);
                    ah[rbase + pos0] = h0; ah[rbase + pos1] = h1;
                    al[rbase + pos0] = l0; al[rbase + pos1] = l1;
                }
                __syncthreads();
            }
        }

        #pragma unroll
        for (int mi = 0; mi < 2; mi++) {
            int r0 = warpRow + mi*16 + g;
            int o0 = s_out[r0], o1 = s_out[r0 + 8];
            #pragma unroll
            for (int ni = 0; ni < 4; ni++) {
                int gn = nh*64 + warpCol + ni*8 + t*2;
                if (o0 >= 0) {
                    atomicAdd(&g_acc[(size_t)o0*PTS_DIM + gn],     acc[mi][ni][0]);
                    atomicAdd(&g_acc[(size_t)o0*PTS_DIM + gn + 1], acc[mi][ni][1]);
                }
                if (o1 >= 0) {
                    atomicAdd(&g_acc[(size_t)o1*PTS_DIM + gn],     acc[mi][ni][2]);
                    atomicAdd(&g_acc[(size_t)o1*PTS_DIM + gn + 1], acc[mi][ni][3]);
                }
            }
        }
    }
}

// ====== conv self: full-N 512-thread kernel (R15), fused g_acc + BN + ReLU ======
__global__ void __launch_bounds__(512, 1)
conv_self_kernel(const float* __restrict__ pts,
                 const int*   __restrict__ vc,
                 float*       __restrict__ out) {
    extern __shared__ char smem[];
    u32* s_bhi = (u32*)(smem + SMF_BHI);
    u32* s_blo = (u32*)(smem + SMF_BLO);
    u32* a_base = (u32*)(smem + SMF_A);
    __shared__ int s_out[128];
    __shared__ int s_nid[128];
    __shared__ float s_sc[128], s_bi[128];

    int tid = threadIdx.x;
    int wid = tid >> 5;
    int lane = tid & 31;
    int g = lane >> 2, t = lane & 3;
    int warpRow = (wid >> 2) * 32;
    int warpCol = (wid & 3) * 32;

    int rw = lane >> 3;
    int cq = lane & 7;
    int arow0 = wid*4 + rw;
    int arow1 = arow0 + 64;
    int pos0 = icol(cq*2), pos1 = icol(cq*2 + 1);

    const int k = 13;
    int np = M_PTS;
    int tile0 = blockIdx.x, tstep = gridDim.x;

    {
        const u32* src_h = (const u32*)(g_wt_hi + (size_t)k*PTS_DIM*KIN);
        const u32* src_l = (const u32*)(g_wt_lo + (size_t)k*PTS_DIM*KIN);
        for (int i = tid; i < 128*112; i += 512) {
            int n = i / 112, kp = i % 112;
            int dst = n*B_S + icol(kp);
            s_bhi[dst] = __ldg(src_h + i);
            s_blo[dst] = __ldg(src_l + i);
        }
        if (tid < 128) { s_sc[tid] = g_bnscale[tid]; s_bi[tid] = g_bnbias[tid]; }
    }
    __syncthreads();

    for (int tile = tile0; tile*128 < np; tile += tstep) {
        __syncthreads();
        if (tid < 128) {
            int r = tile*128 + tid;
            int o = -1, nid = 0;
            if (r < np) {
                int4 c4 = ((const int4*)vc)[r];
                o = r;
                nid = __ldg(&g_grid[(c4.y*GY + c4.z)*GX + c4.w]);
            }
            s_out[tid] = o;
            s_nid[tid] = nid;
        }
        __syncthreads();

        float acc[2][4][4];
        #pragma unroll
        for (int mi = 0; mi < 2; mi++)
            #pragma unroll
            for (int ni = 0; ni < 4; ni++)
                #pragma unroll
                for (int j = 0; j < 4; j++) acc[mi][ni][j] = 0.0f;

        int nid0 = s_nid[arow0], nid1 = s_nid[arow1];
        const float* rp0 = pts + (size_t)nid0*PTS_DIM;
        const float* rs0 = g_sampled + (size_t)nid0*C_IMG - PTS_DIM;
        const float* rp1 = pts + (size_t)nid1*PTS_DIM;
        const float* rs1 = g_sampled + (size_t)nid1*C_IMG - PTS_DIM;

        float4 v0, v1;
        {
            int fcol = cq*4;
            v0 = __ldg((const float4*)(rp0 + fcol));
            v1 = __ldg((const float4*)(rp1 + fcol));
            u32* ah = a_base;
            u32* al = a_base + A_BUF_U32;
            u32 h0,l0,h1,l1;
            split2(v0.x, v0.y, h0, l0); split2(v0.z, v0.w, h1, l1);
            ah[arow0*A2_S + pos0] = h0; ah[arow0*A2_S + pos1] = h1;
            al[arow0*A2_S + pos0] = l0; al[arow0*A2_S + pos1] = l1;
            split2(v1.x, v1.y, h0, l0); split2(v1.z, v1.w, h1, l1);
            ah[arow1*A2_S + pos0] = h0; ah[arow1*A2_S + pos1] = h1;
            al[arow1*A2_S + pos0] = l0; al[arow1*A2_S + pos1] = l1;
        }
        __syncthreads();

        #pragma unroll 1
        for (int p = 0; p < 7; p++) {
            if (p < 6) {
                int fcol = (p+1)*32 + cq*4;
                const float* s0 = (fcol < PTS_DIM) ? (rp0 + fcol) : (rs0 + fcol);
                const float* s1 = (fcol < PTS_DIM) ? (rp1 + fcol) : (rs1 + fcol);
                v0 = __ldg((const float4*)s0);
                v1 = __ldg((const float4*)s1);
            }
            {
                const u32* ah = a_base + (p & 1)*2*A_BUF_U32;
                const u32* al = ah + A_BUF_U32;
                #pragma unroll
                for (int cl = 0; cl < 2; cl++) {
                    int cg = p*2 + cl;
                    u32 fa_h[2][4], fa_l[2][4];
                    #pragma unroll
                    for (int mi = 0; mi < 2; mi++) {
                        int r0 = warpRow + mi*16 + g;
                        int off0 = r0*A2_S + cl*8 + 2*t;
                        int off1 = off0 + 8*A2_S;
                        uint2 ph0 = *(const uint2*)&ah[off0];
                        uint2 ph1 = *(const uint2*)&ah[off1];
                        uint2 pl0 = *(const uint2*)&al[off0];
                        uint2 pl1 = *(const uint2*)&al[off1];
                        fa_h[mi][0] = ph0.x; fa_h[mi][2] = ph0.y;
                        fa_h[mi][1] = ph1.x; fa_h[mi][3] = ph1.y;
                        fa_l[mi][0] = pl0.x; fa_l[mi][2] = pl0.y;
                        fa_l[mi][1] = pl1.x; fa_l[mi][3] = pl1.y;
                    }
                    #pragma unroll
                    for (int ni = 0; ni < 4; ni++) {
                        int n = warpCol + ni*8 + g;
                        int off = n*B_S + cg*8 + 2*t;
                        uint2 bh = *(const uint2*)&s_bhi[off];
                        uint2 bl = *(const uint2*)&s_blo[off];
                        #pragma unroll
                        for (int mi = 0; mi < 2; mi++) {
                            MMA_BF16(acc[mi][ni], fa_h[mi], bh.x, bh.y);
                            MMA_BF16(acc[mi][ni], fa_h[mi], bl.x, bl.y);
                            MMA_BF16(acc[mi][ni], fa_l[mi], bh.x, bh.y);
                        }
                    }
                }
            }
            if (p < 6) {
                u32* ah = a_base + ((p+1) & 1)*2*A_BUF_U32;
                u32* al = ah + A_BUF_U32;
                u32 h0,l0,h1,l1;
                split2(v0.x, v0.y, h0, l0); split2(v0.z, v0.w, h1, l1);
                ah[arow0*A2_S + pos0] = h0; ah[arow0*A2_S + pos1] = h1;
                al[arow0*A2_S + pos0] = l0; al[arow0*A2_S + pos1] = l1;
                split2(v1.x, v1.y, h0, l0); split2(v1.z, v1.w, h1, l1);
                ah[arow1*A2_S + pos0] = h0; ah[arow1*A2_S + pos1] = h1;
                al[arow1*A2_S + pos0] = l0; al[arow1*A2_S + pos1] = l1;
                __syncthreads();
            }
        }

        #pragma unroll
        for (int mi = 0; mi < 2; mi++) {
            int r0 = warpRow + mi*16 + g;
            int o0 = s_out[r0], o1 = s_out[r0 + 8];
            #pragma unroll
            for (int ni = 0; ni < 4; ni++) {
                int n0 = warpCol + ni*8 + t*2;
                float sc0 = s_sc[n0], sc1 = s_sc[n0+1];
                float bi0 = s_bi[n0], bi1 = s_bi[n0+1];
                if (o0 >= 0) {
                    float a0 = g_acc[(size_t)o0*PTS_DIM + n0];
                    float a1 = g_acc[(size_t)o0*PTS_DIM + n0 + 1];
                    out[(size_t)o0*PTS_DIM + n0]     = fmaxf((acc[mi][ni][0]+a0)*sc0+bi0, 0.f);
                    out[(size_t)o0*PTS_DIM + n0 + 1] = fmaxf((acc[mi][ni][1]+a1)*sc1+bi1, 0.f);
                }
                if (o1 >= 0) {
                    float a2 = g_acc[(size_t)o1*PTS_DIM + n0];
                    float a3 = g_acc[(size_t)o1*PTS_DIM + n0 + 1];
                    out[(size_t)o1*PTS_DIM + n0]     = fmaxf((acc[mi][ni][2]+a2)*sc0+bi0, 0.f);
                    out[(size_t)o1*PTS_DIM + n0 + 1] = fmaxf((acc[mi][ni][3]+a3)*sc1+bi1, 0.f);
                }
            }
        }
    }
}

// ---------------- launch ----------------
extern "C" void kernel_launch(void* const* d_in, const int* in_sizes, int n_in,
                              void* d_out, int out_size) {
    const float* pts   = (const float*)d_in[0];
    const int*   vc    = (const int*)  d_in[1];
    const float* img   = (const float*)d_in[2];
    const float* l2i   = (const float*)d_in[3];
    const float* iaug  = (const float*)d_in[4];
    const float* laug  = (const float*)d_in[5];
    const float* convw = (const float*)d_in[6];
    const float* gamma = (const float*)d_in[7];
    const float* beta  = (const float*)d_in[8];
    const float* mean  = (const float*)d_in[9];
    const float* var   = (const float*)d_in[10];
    float* out = (float*)d_out;

    cudaFuncSetAttribute(conv_split_kernel, cudaFuncAttributeMaxDynamicSharedMemorySize, SMEM_SPLIT);
    cudaFuncSetAttribute(conv_self_kernel,  cudaFuncAttributeMaxDynamicSharedMemorySize, SMEM_FULL);

    mega_setup_kernel<<<NB_MEGA1, 256>>>(img, convw, l2i, iaug, laug, gamma, beta, mean, var);
    scatter_kernel<<<(M_PTS + 255)/256, 256>>>(vc);
    mega_mid_kernel<<<NB_MEGA2, 256>>>(vc);
    conv_split_kernel<<<dim3(20, NTAP_O, 2), 256, SMEM_SPLIT>>>(pts, vc, out);   // <-- ncu slot
    conv_self_kernel <<<dim3(148, 1),        512, SMEM_FULL >>>(pts, vc, out);
}